// round 15
// baseline (speedup 1.0000x reference)
#include <cuda_runtime.h>
#include <cuda_fp16.h>
#include <cstdint>

// ---------------------------------------------------------------------------
// AxialAttention via warp-level tensor cores (mma.sync m16n8k16 f16->f32).
// R15 = R13 design, second resubmission (broker container failures only;
// zero kernel-side evidence across eight such failures this session).
//  (a) head loop fully unrolled -> qreg/oa statically indexed (no local-
//      memory demotion); (b) all B fragments via ldmatrix.x4 (2 n-octets
//      per instruction) -> B-side ldsm count halved. Structure = R12:
//      3 smem tiles, 2 CTAs/SM, barrier-free attention, Oa in registers.
// ---------------------------------------------------------------------------

#define NTHREADS 256
#define HS 136                       // halfs per tile row (272B: ldmatrix conflict-free)
static constexpr int TILE = 128 * HS;
static constexpr int SMEM_BYTES = 3 * TILE * 2;   // 104,448 B -> 2 CTAs/SM

__device__ __forceinline__ uint32_t sptr(const void* p) {
    return (uint32_t)__cvta_generic_to_shared(p);
}
__device__ __forceinline__ void ldsm_x4(uint32_t r[4], uint32_t a) {
    asm volatile("ldmatrix.sync.aligned.m8n8.x4.shared.b16 {%0,%1,%2,%3}, [%4];"
                 : "=r"(r[0]), "=r"(r[1]), "=r"(r[2]), "=r"(r[3]) : "r"(a));
}
__device__ __forceinline__ void ldsm_x4t(uint32_t r[4], uint32_t a) {
    asm volatile("ldmatrix.sync.aligned.m8n8.x4.trans.shared.b16 {%0,%1,%2,%3}, [%4];"
                 : "=r"(r[0]), "=r"(r[1]), "=r"(r[2]), "=r"(r[3]) : "r"(a));
}
__device__ __forceinline__ void mma_f16(float c[4], const uint32_t a[4],
                                        uint32_t b0, uint32_t b1) {
    asm volatile(
        "mma.sync.aligned.m16n8k16.row.col.f32.f16.f16.f32 "
        "{%0,%1,%2,%3}, {%4,%5,%6,%7}, {%8,%9}, {%0,%1,%2,%3};"
        : "+f"(c[0]), "+f"(c[1]), "+f"(c[2]), "+f"(c[3])
        : "r"(a[0]), "r"(a[1]), "r"(a[2]), "r"(a[3]), "r"(b0), "r"(b1));
}
__device__ __forceinline__ uint32_t packh2(float a, float b) {
    __half2 h = __floats2half2_rn(a, b);
    return *reinterpret_cast<uint32_t*>(&h);
}
__device__ __forceinline__ float2 unpackh2(uint32_t u) {
    __half2 h = *reinterpret_cast<__half2*>(&u);
    return __half22float2(h);
}
// Stage one 64-float half-row: fp32 global -> fp16 smem tile [r][hf*64 ..+63].
__device__ __forceinline__ void stage_row(__half* tile, const float* src, int r, int hf) {
    const float4* s4 = reinterpret_cast<const float4*>(src);
    uint4* d4 = reinterpret_cast<uint4*>(tile + r * HS + hf * 64);
    #pragma unroll
    for (int i = 0; i < 8; i++) {
        float4 a = s4[2 * i], c = s4[2 * i + 1];
        uint4 u;
        u.x = packh2(a.x, a.y); u.y = packh2(a.z, a.w);
        u.z = packh2(c.x, c.y); u.w = packh2(c.z, c.w);
        d4[i] = u;
    }
}

template <int PASS>
__global__ __launch_bounds__(NTHREADS, 2)
void axial_attn_kernel(const float* __restrict__ x,
                       const float* __restrict__ Wq,
                       const float* __restrict__ Wkv,
                       const float* __restrict__ Wo,
                       const float* __restrict__ bo,
                       float* __restrict__ out)
{
    extern __shared__ __half smh[];
    __half* T0 = smh;              // X -> Wk -> Wv -> Wq -> Wo
    __half* T1 = smh + TILE;       // K (read-only after projection)
    __half* T2 = smh + 2 * TILE;   // V

    const int t    = threadIdx.x;
    const int w    = t >> 5;
    const int lane = t & 31;
    const int lr   = lane & 7;
    const int lg   = lane >> 3;          // ldmatrix group 0..3
    const int lq   = lane >> 2;          // C-frag row-in-8
    const int lc   = lane & 3;           // C-frag col pair
    const int m0   = w * 16;             // warp row strip

    const int seq = blockIdx.x;
    const int bb  = seq >> 7;
    const int s   = seq & 127;
    const int base    = bb * (128 * 128 * 128) + (PASS == 0 ? s * 128 : s * 16384);
    const int istride = (PASS == 0 ? 16384 : 128);

    const int sr = t >> 1, shf = t & 1;   // staging row / half

    // x4 B addressing: row within 16-k block + col-octet select
    const int brow = ((lg & 1) << 3) + lr;   // (lg&1)*8 + lr
    const int bco  = (lg >> 1) << 3;         // col-octet offset 0 / 8

    // ---- Stage X into T0 ----
    stage_row(T0, x + base + sr * istride + shf * 64, sr, shf);
    __syncthreads();

    const uint32_t aoff  = (m0 + lr + ((lg & 1) << 3)) * HS + ((lg >> 1) << 3);
    const uint32_t xaddr = sptr(T0 + aoff);

    // X A-fragments (live through the three projection GEMMs)
    uint32_t xa[8][4];
    #pragma unroll
    for (int kb = 0; kb < 8; kb++) ldsm_x4(xa[kb], xaddr + kb * 32);
    __syncthreads();   // T0 free for weights

    // ---- K projection ----
    stage_row(T0, Wkv + sr * 256 + shf * 64, sr, shf);
    __syncthreads();
    #pragma unroll
    for (int np = 0; np < 8; np++) {
        float ce[4] = {0.f, 0.f, 0.f, 0.f}, co[4] = {0.f, 0.f, 0.f, 0.f};
        #pragma unroll
        for (int kb = 0; kb < 8; kb++) {
            uint32_t bf[4];
            ldsm_x4t(bf, sptr(T0 + (kb * 16 + brow) * HS + np * 16 + bco));
            mma_f16(ce, xa[kb], bf[0], bf[1]);
            mma_f16(co, xa[kb], bf[2], bf[3]);
        }
        *reinterpret_cast<uint32_t*>(T1 + (m0 + lq)     * HS + np * 16 +     2 * lc) = packh2(ce[0], ce[1]);
        *reinterpret_cast<uint32_t*>(T1 + (m0 + lq + 8) * HS + np * 16 +     2 * lc) = packh2(ce[2], ce[3]);
        *reinterpret_cast<uint32_t*>(T1 + (m0 + lq)     * HS + np * 16 + 8 + 2 * lc) = packh2(co[0], co[1]);
        *reinterpret_cast<uint32_t*>(T1 + (m0 + lq + 8) * HS + np * 16 + 8 + 2 * lc) = packh2(co[2], co[3]);
    }
    __syncthreads();

    // ---- V projection ----
    stage_row(T0, Wkv + sr * 256 + 128 + shf * 64, sr, shf);
    __syncthreads();
    #pragma unroll
    for (int np = 0; np < 8; np++) {
        float ce[4] = {0.f, 0.f, 0.f, 0.f}, co[4] = {0.f, 0.f, 0.f, 0.f};
        #pragma unroll
        for (int kb = 0; kb < 8; kb++) {
            uint32_t bf[4];
            ldsm_x4t(bf, sptr(T0 + (kb * 16 + brow) * HS + np * 16 + bco));
            mma_f16(ce, xa[kb], bf[0], bf[1]);
            mma_f16(co, xa[kb], bf[2], bf[3]);
        }
        *reinterpret_cast<uint32_t*>(T2 + (m0 + lq)     * HS + np * 16 +     2 * lc) = packh2(ce[0], ce[1]);
        *reinterpret_cast<uint32_t*>(T2 + (m0 + lq + 8) * HS + np * 16 +     2 * lc) = packh2(ce[2], ce[3]);
        *reinterpret_cast<uint32_t*>(T2 + (m0 + lq)     * HS + np * 16 + 8 + 2 * lc) = packh2(co[0], co[1]);
        *reinterpret_cast<uint32_t*>(T2 + (m0 + lq + 8) * HS + np * 16 + 8 + 2 * lc) = packh2(co[2], co[3]);
    }
    __syncthreads();

    // ---- Q projection (registers only; scale folded) ----
    stage_row(T0, Wq + sr * 128 + shf * 64, sr, shf);
    __syncthreads();
    uint32_t qreg[16][2];
    #pragma unroll
    for (int np = 0; np < 8; np++) {
        float ce[4] = {0.f, 0.f, 0.f, 0.f}, co[4] = {0.f, 0.f, 0.f, 0.f};
        #pragma unroll
        for (int kb = 0; kb < 8; kb++) {
            uint32_t bf[4];
            ldsm_x4t(bf, sptr(T0 + (kb * 16 + brow) * HS + np * 16 + bco));
            mma_f16(ce, xa[kb], bf[0], bf[1]);
            mma_f16(co, xa[kb], bf[2], bf[3]);
        }
        qreg[2 * np][0]     = packh2(ce[0] * 0.25f, ce[1] * 0.25f);   // 1/sqrt(16)
        qreg[2 * np][1]     = packh2(ce[2] * 0.25f, ce[3] * 0.25f);
        qreg[2 * np + 1][0] = packh2(co[0] * 0.25f, co[1] * 0.25f);
        qreg[2 * np + 1][1] = packh2(co[2] * 0.25f, co[3] * 0.25f);
    }
    __syncthreads();

    // ---- Stage Wo into T0 (read-only through phases 3-4) ----
    stage_row(T0, Wo + sr * 128 + shf * 64, sr, shf);
    __syncthreads();
    // NO MORE CTA BARRIERS from here to the end.

    // ---- Phase 3: attention; Oa accumulated in registers (A-frags for phase 4) ----
    uint32_t oa[8][4];
    #pragma unroll
    for (int h = 0; h < 8; h++) {
        uint32_t sp[16][2];               // S then P, packed fp16
        float mx0 = -1e30f, mx1 = -1e30f;
        #pragma unroll
        for (int np = 0; np < 8; np++) {
            // K non-trans x4: 2 key-octets x (dims 0-7 / 8-15)
            uint32_t bf[4];
            ldsm_x4(bf, sptr(T1 + (np * 16 + ((lg >> 1) << 3) + lr) * HS + h * 16 + ((lg & 1) << 3)));
            float c0[4] = {0.f, 0.f, 0.f, 0.f}, c1[4] = {0.f, 0.f, 0.f, 0.f};
            mma_f16(c0, qreg[2 * h], bf[0], bf[1]);
            mma_f16(c1, qreg[2 * h], bf[2], bf[3]);
            mx0 = fmaxf(mx0, fmaxf(fmaxf(c0[0], c0[1]), fmaxf(c1[0], c1[1])));
            mx1 = fmaxf(mx1, fmaxf(fmaxf(c0[2], c0[3]), fmaxf(c1[2], c1[3])));
            sp[2 * np][0]     = packh2(c0[0], c0[1]);
            sp[2 * np][1]     = packh2(c0[2], c0[3]);
            sp[2 * np + 1][0] = packh2(c1[0], c1[1]);
            sp[2 * np + 1][1] = packh2(c1[2], c1[3]);
        }
        mx0 = fmaxf(mx0, __shfl_xor_sync(0xffffffffu, mx0, 1));
        mx0 = fmaxf(mx0, __shfl_xor_sync(0xffffffffu, mx0, 2));
        mx1 = fmaxf(mx1, __shfl_xor_sync(0xffffffffu, mx1, 1));
        mx1 = fmaxf(mx1, __shfl_xor_sync(0xffffffffu, mx1, 2));

        float l0 = 0.f, l1 = 0.f;
        #pragma unroll
        for (int nt = 0; nt < 16; nt++) {
            float2 a = unpackh2(sp[nt][0]);
            float2 b = unpackh2(sp[nt][1]);
            float e0 = __expf(a.x - mx0), e1 = __expf(a.y - mx0);
            float e2 = __expf(b.x - mx1), e3 = __expf(b.y - mx1);
            l0 += e0 + e1; l1 += e2 + e3;
            sp[nt][0] = packh2(e0, e1);
            sp[nt][1] = packh2(e2, e3);
        }
        l0 += __shfl_xor_sync(0xffffffffu, l0, 1);
        l0 += __shfl_xor_sync(0xffffffffu, l0, 2);
        l1 += __shfl_xor_sync(0xffffffffu, l1, 1);
        l1 += __shfl_xor_sync(0xffffffffu, l1, 2);

        // P @ V  (V x4t: dims octets h*16+0..7 / +8..15 per k-block)
        float o0[4] = {0.f, 0.f, 0.f, 0.f}, o1[4] = {0.f, 0.f, 0.f, 0.f};
        #pragma unroll
        for (int kb = 0; kb < 8; kb++) {
            uint32_t bf[4];
            ldsm_x4t(bf, sptr(T2 + (kb * 16 + brow) * HS + h * 16 + bco));
            mma_f16(o0, sp[2 * kb], bf[0], bf[1]);
            mma_f16(o1, sp[2 * kb], bf[2], bf[3]);
        }
        const float i0 = 1.0f / l0, i1 = 1.0f / l1;
        // PV C-frag == out-proj A-frag for k-block h
        oa[h][0] = packh2(o0[0] * i0, o0[1] * i0);
        oa[h][1] = packh2(o0[2] * i1, o0[3] * i1);
        oa[h][2] = packh2(o1[0] * i0, o1[1] * i0);
        oa[h][3] = packh2(o1[2] * i1, o1[3] * i1);
    }

    // ---- Phase 4: out-projection + bias (+pass1 accumulate); A from registers ----
    #pragma unroll
    for (int np = 0; np < 8; np++) {
        float ce[4] = {0.f, 0.f, 0.f, 0.f}, co[4] = {0.f, 0.f, 0.f, 0.f};
        #pragma unroll
        for (int kb = 0; kb < 8; kb++) {
            uint32_t bf[4];
            ldsm_x4t(bf, sptr(T0 + (kb * 16 + brow) * HS + np * 16 + bco));
            mma_f16(ce, oa[kb], bf[0], bf[1]);
            mma_f16(co, oa[kb], bf[2], bf[3]);
        }
        #pragma unroll
        for (int half = 0; half < 2; half++) {
            const float* cc = half ? co : ce;
            const int col = np * 16 + half * 8 + 2 * lc;
            const float2 bv = *reinterpret_cast<const float2*>(bo + col);
            float* p0 = out + base + (m0 + lq)     * istride + col;
            float* p1 = out + base + (m0 + lq + 8) * istride + col;
            float2 w0 = make_float2(cc[0] + bv.x, cc[1] + bv.y);
            float2 w1 = make_float2(cc[2] + bv.x, cc[3] + bv.y);
            if (PASS == 1) {
                float2 q0 = *reinterpret_cast<const float2*>(p0);
                float2 q1 = *reinterpret_cast<const float2*>(p1);
                w0.x += q0.x; w0.y += q0.y;
                w1.x += q1.x; w1.y += q1.y;
            }
            *reinterpret_cast<float2*>(p0) = w0;
            *reinterpret_cast<float2*>(p1) = w1;
        }
    }
}

extern "C" void kernel_launch(void* const* d_in, const int* in_sizes, int n_in,
                              void* d_out, int out_size)
{
    const float* x    = (const float*)d_in[0];
    const float* Wq0  = (const float*)d_in[1];
    const float* Wkv0 = (const float*)d_in[2];
    const float* Wo0  = (const float*)d_in[3];
    const float* bo0  = (const float*)d_in[4];
    const float* Wq1  = (const float*)d_in[5];
    const float* Wkv1 = (const float*)d_in[6];
    const float* Wo1  = (const float*)d_in[7];
    const float* bo1  = (const float*)d_in[8];
    float* out = (float*)d_out;

    cudaFuncSetAttribute(axial_attn_kernel<0>,
                         cudaFuncAttributeMaxDynamicSharedMemorySize, SMEM_BYTES);
    cudaFuncSetAttribute(axial_attn_kernel<1>,
                         cudaFuncAttributeMaxDynamicSharedMemorySize, SMEM_BYTES);

    axial_attn_kernel<0><<<1024, NTHREADS, SMEM_BYTES>>>(x, Wq0, Wkv0, Wo0, bo0, out);
    axial_attn_kernel<1><<<1024, NTHREADS, SMEM_BYTES>>>(x, Wq1, Wkv1, Wo1, bo1, out);
}